// round 13
// baseline (speedup 1.0000x reference)
#include <cuda_runtime.h>

#define N_NODES   100000
#define N_EDGES   1600000
#define NFEAT     48
#define HIDDEN    256
#define TPB       256
#define EPT       16                                   // edges per thread
#define EDGE_ITEMS  (N_EDGES / EPT)                    // 100000
#define EDGE_BLOCKS ((EDGE_ITEMS + TPB - 1) / TPB)     // 391  -> single wave
#define NODE_BLOCKS ((N_NODES + TPB - 1) / TPB)        // 391

// Device scratch. Zero-initialized at module load. Per-call invariants:
//   g_deg: zero at entry (k_zy zeroes it after its final read each call)
//   g_s:   seeded to z by k_zy before k_edges' post-sync atomics (PDL order)
// => every call observes identical state: deterministic.
__device__ float g_deg[N_NODES];   // per-destination edge count
__device__ float g_dinv[N_NODES];  // rsqrt(deg+1)
__device__ float g_z[N_NODES];     // dinv * (x @ W1@W2)
__device__ float g_s[N_NODES];     // z[c] + sum_{r->c} z[r]

// ---------------------------------------------------------------------------
// K1: pure degree histogram, 16 edges/thread (4x int4), single wave.
// ---------------------------------------------------------------------------
__global__ void __launch_bounds__(TPB) k_deg(const int* __restrict__ ei)
{
    if (threadIdx.x == 0) cudaTriggerProgrammaticLaunchCompletion();
    int tid = blockIdx.x * TPB + threadIdx.x;
    if (tid >= EDGE_ITEMS) return;
    const int4* cols = reinterpret_cast<const int4*>(ei + N_EDGES);
    #pragma unroll
    for (int q = 0; q < 4; q++) {
        int4 c = cols[4 * tid + q];
        atomicAdd(&g_deg[c.x], 1.0f);
        atomicAdd(&g_deg[c.y], 1.0f);
        atomicAdd(&g_deg[c.z], 1.0f);
        atomicAdd(&g_deg[c.w], 1.0f);
    }
}

// ---------------------------------------------------------------------------
// K2 (PDL): prelude (overlaps K1): fold w = W1@W2 per block, stream x,
//   accumulate y in REGISTERS. Post-sync: z = rsqrt(deg+1)*y; store z, dinv;
//   seed s = z (self-loop); zero g_deg (last reader).
// ---------------------------------------------------------------------------
__global__ void __launch_bounds__(TPB) k_zy(const float* __restrict__ x,
                                            const float* __restrict__ W1,
                                            const float* __restrict__ W2)
{
    if (threadIdx.x == 0) cudaTriggerProgrammaticLaunchCompletion();

    __shared__ float sW2[HIDDEN];
    __shared__ float sw[NFEAT];
    int t = threadIdx.x;
    sW2[t] = W2[t];
    __syncthreads();

    int warp = t >> 5, lane = t & 31;
    for (int f = warp; f < NFEAT; f += 8) {
        float p = 0.0f;
        #pragma unroll
        for (int h = lane; h < HIDDEN; h += 32)
            p += W1[f * HIDDEN + h] * sW2[h];
        #pragma unroll
        for (int o = 16; o; o >>= 1)
            p += __shfl_down_sync(0xffffffffu, p, o);
        if (lane == 0) sw[f] = p;
    }
    __syncthreads();

    int i = blockIdx.x * TPB + t;
    float acc = 0.0f;
    if (i < N_NODES) {
        const float4* xr = reinterpret_cast<const float4*>(x + (size_t)i * NFEAT);
        #pragma unroll
        for (int j = 0; j < NFEAT / 4; j++) {
            float4 v = xr[j];
            acc += v.x * sw[4 * j + 0] + v.y * sw[4 * j + 1]
                 + v.z * sw[4 * j + 2] + v.w * sw[4 * j + 3];
        }
    }

    cudaGridDependencySynchronize();          // wait for all degrees

    if (i >= N_NODES) return;
    float d = rsqrtf(g_deg[i] + 1.0f);
    float z = d * acc;
    g_dinv[i] = d;
    g_z[i]    = z;
    g_s[i]    = z;                     // accumulator seeded w/ self-loop term
    g_deg[i]  = 0.0f;                  // reset invariant for next call
}

// ---------------------------------------------------------------------------
// K3 (PDL): prelude: load 16 edges of indices (overlaps K1/K2); post-sync:
//           scatter s[c] += z[r].
// ---------------------------------------------------------------------------
__global__ void __launch_bounds__(TPB) k_edges(const int* __restrict__ ei)
{
    if (threadIdx.x == 0) cudaTriggerProgrammaticLaunchCompletion();
    int tid = blockIdx.x * TPB + threadIdx.x;
    bool active = (tid < EDGE_ITEMS);
    int4 r[4], c[4];
    if (active) {
        const int4* rows = reinterpret_cast<const int4*>(ei);
        const int4* cols = reinterpret_cast<const int4*>(ei + N_EDGES);
        #pragma unroll
        for (int q = 0; q < 4; q++) {
            r[q] = rows[4 * tid + q];
            c[q] = cols[4 * tid + q];
        }
    }
    cudaGridDependencySynchronize();
    if (!active) return;

    #pragma unroll
    for (int q = 0; q < 4; q++) {
        float z0 = __ldg(&g_z[r[q].x]);
        float z1 = __ldg(&g_z[r[q].y]);
        float z2 = __ldg(&g_z[r[q].z]);
        float z3 = __ldg(&g_z[r[q].w]);
        atomicAdd(&g_s[c[q].x], z0);
        atomicAdd(&g_s[c[q].y], z1);
        atomicAdd(&g_s[c[q].z], z2);
        atomicAdd(&g_s[c[q].w], z3);
    }
}

// ---------------------------------------------------------------------------
// K4 (PDL): prelude: cterm reduction (hidden); post-sync minimal tail:
//           out = dinv*s + cterm.  2 coalesced loads + 1 FMA + 1 store.
// ---------------------------------------------------------------------------
__global__ void __launch_bounds__(TPB) k_final(float*       __restrict__ out,
                                               const float* __restrict__ bias,
                                               const float* __restrict__ W2,
                                               const float* __restrict__ b2)
{
    __shared__ float sred[TPB];
    int t = threadIdx.x;
    sred[t] = W2[t];                      // inputs only: safe pre-sync
    float b0 = bias[0], b20 = b2[0];
    __syncthreads();
    for (int s = TPB / 2; s > 0; s >>= 1) {
        if (t < s) sred[t] += sred[t + s];
        __syncthreads();
    }
    float cterm = b0 * sred[0] + b20;

    cudaGridDependencySynchronize();

    int i = blockIdx.x * TPB + t;
    if (i >= N_NODES) return;
    out[i] = fmaf(g_dinv[i], g_s[i], cterm);
}

// ---------------------------------------------------------------------------
extern "C" void kernel_launch(void* const* d_in, const int* in_sizes, int n_in,
                              void* d_out, int out_size)
{
    const float* x    = (const float*)d_in[0];   // [N, 48]
    const int*   ei   = (const int*)  d_in[1];   // [2, E]
    const float* W1   = (const float*)d_in[2];   // [48, 256]
    const float* bias = (const float*)d_in[3];   // [1]
    const float* W2   = (const float*)d_in[4];   // [256, 1]
    const float* b2   = (const float*)d_in[5];   // [1]
    float* out = (float*)d_out;                  // [N, 1]

    k_deg<<<EDGE_BLOCKS, TPB>>>(ei);

    cudaLaunchAttribute at;
    at.id = cudaLaunchAttributeProgrammaticStreamSerialization;
    at.val.programmaticStreamSerializationAllowed = 1;

    cudaLaunchConfig_t cfg = {};
    cfg.blockDim = dim3(TPB, 1, 1);
    cfg.attrs    = &at;
    cfg.numAttrs = 1;
    cfg.stream   = (cudaStream_t)0;

    cfg.gridDim = dim3(NODE_BLOCKS, 1, 1);
    cudaLaunchKernelEx(&cfg, k_zy, x, W1, W2);

    cfg.gridDim = dim3(EDGE_BLOCKS, 1, 1);
    cudaLaunchKernelEx(&cfg, k_edges, ei);

    cfg.gridDim = dim3(NODE_BLOCKS, 1, 1);
    cudaLaunchKernelEx(&cfg, k_final, out, bias, W2, b2);
}

// round 14
// speedup vs baseline: 1.0555x; 1.0555x over previous
#include <cuda_runtime.h>

#define N_NODES   100000
#define N_EDGES   1600000
#define NFEAT     48
#define HIDDEN    256
#define TPB       256
#define EPT       8                                    // edges per thread
#define EDGE_ITEMS  (N_EDGES / EPT)                    // 200000
#define EDGE_BLOCKS ((EDGE_ITEMS + TPB - 1) / TPB)     // 782
#define NODE_BLOCKS ((N_NODES + TPB - 1) / TPB)        // 391
#define K1_BLOCKS   (EDGE_BLOCKS + NODE_BLOCKS)        // 1173 = 3*391

// Device scratch. Zero-initialized at module load. Per-call invariants:
//   g_deg: zero at entry (k_z zeroes it after its final read each call)
//   g_s:   seeded to z by k_z before k_edges' post-sync atomics (PDL order)
// => every call observes identical state: deterministic.
__device__ float g_deg[N_NODES];   // per-destination edge count
__device__ float g_y[N_NODES];     // x @ (W1@W2)
__device__ float g_dinv[N_NODES];  // rsqrt(deg+1)
__device__ float g_z[N_NODES];     // dinv * y
__device__ float g_s[N_NODES];     // z[c] + sum_{r->c} z[r]

// ---------------------------------------------------------------------------
// K1: role-interleaved grid (2 deg blocks : 1 y block by bid%3) so both the
//     L2-atomic degree histogram and the DRAM x-stream are resident in wave 1
//     and overlap on disjoint resources.
// ---------------------------------------------------------------------------
__global__ void __launch_bounds__(TPB) k_deg_y(const int*   __restrict__ ei,
                                               const float* __restrict__ x,
                                               const float* __restrict__ W1,
                                               const float* __restrict__ W2)
{
    if (threadIdx.x == 0) cudaTriggerProgrammaticLaunchCompletion();

    const int r = blockIdx.x % 3;
    const int q = blockIdx.x / 3;          // 0..390

    if (r < 2) {
        // ---- degree histogram block (eb in [0, 782)) ----
        int eb  = 2 * q + r;
        int tid = eb * TPB + threadIdx.x;
        if (tid >= EDGE_ITEMS) return;
        const int4* cols = reinterpret_cast<const int4*>(ei + N_EDGES);
        int4 a = cols[2 * tid + 0];
        int4 c = cols[2 * tid + 1];
        atomicAdd(&g_deg[a.x], 1.0f);
        atomicAdd(&g_deg[a.y], 1.0f);
        atomicAdd(&g_deg[a.z], 1.0f);
        atomicAdd(&g_deg[a.w], 1.0f);
        atomicAdd(&g_deg[c.x], 1.0f);
        atomicAdd(&g_deg[c.y], 1.0f);
        atomicAdd(&g_deg[c.z], 1.0f);
        atomicAdd(&g_deg[c.w], 1.0f);
        return;
    }

    // ---- y block (yb = q in [0, 391)) ----
    __shared__ float sW2[HIDDEN];
    __shared__ float sw[NFEAT];
    int t = threadIdx.x;
    sW2[t] = W2[t];
    __syncthreads();

    int warp = t >> 5, lane = t & 31;
    for (int f = warp; f < NFEAT; f += 8) {
        float p = 0.0f;
        #pragma unroll
        for (int h = lane; h < HIDDEN; h += 32)
            p += W1[f * HIDDEN + h] * sW2[h];
        #pragma unroll
        for (int o = 16; o; o >>= 1)
            p += __shfl_down_sync(0xffffffffu, p, o);
        if (lane == 0) sw[f] = p;
    }
    __syncthreads();

    int i = q * TPB + t;
    if (i >= N_NODES) return;
    const float4* xr = reinterpret_cast<const float4*>(x + (size_t)i * NFEAT);
    float acc = 0.0f;
    #pragma unroll
    for (int j = 0; j < NFEAT / 4; j++) {
        float4 v = xr[j];
        acc += v.x * sw[4 * j + 0] + v.y * sw[4 * j + 1]
             + v.z * sw[4 * j + 2] + v.w * sw[4 * j + 3];
    }
    g_y[i] = acc;
}

// ---------------------------------------------------------------------------
// K2 (PDL): post-sync tail only: d = rsqrt(deg+1); z = d*y; store dinv,z;
//   seed s = z (self-loop term); zero g_deg (last reader).
// ---------------------------------------------------------------------------
__global__ void __launch_bounds__(TPB) k_z()
{
    if (threadIdx.x == 0) cudaTriggerProgrammaticLaunchCompletion();
    cudaGridDependencySynchronize();
    int i = blockIdx.x * TPB + threadIdx.x;
    if (i >= N_NODES) return;
    float d = rsqrtf(g_deg[i] + 1.0f);
    float z = d * g_y[i];
    g_dinv[i] = d;
    g_z[i]    = z;
    g_s[i]    = z;                     // accumulator seeded w/ self-loop term
    g_deg[i]  = 0.0f;                  // reset invariant for next call
}

// ---------------------------------------------------------------------------
// K3 (PDL): prelude: load edge indices (overlaps K1/K2); post-sync: scatter
//           s[c] += z[r]  (8 edges/thread).
// ---------------------------------------------------------------------------
__global__ void __launch_bounds__(TPB) k_edges(const int* __restrict__ ei)
{
    if (threadIdx.x == 0) cudaTriggerProgrammaticLaunchCompletion();
    int tid = blockIdx.x * TPB + threadIdx.x;
    bool active = (tid < EDGE_ITEMS);
    int4 r0, r1, c0, c1;
    if (active) {
        const int4* rows = reinterpret_cast<const int4*>(ei);
        const int4* cols = reinterpret_cast<const int4*>(ei + N_EDGES);
        r0 = rows[2 * tid + 0];
        r1 = rows[2 * tid + 1];
        c0 = cols[2 * tid + 0];
        c1 = cols[2 * tid + 1];
    }
    cudaGridDependencySynchronize();
    if (!active) return;

    float z0 = __ldg(&g_z[r0.x]);
    float z1 = __ldg(&g_z[r0.y]);
    float z2 = __ldg(&g_z[r0.z]);
    float z3 = __ldg(&g_z[r0.w]);
    float z4 = __ldg(&g_z[r1.x]);
    float z5 = __ldg(&g_z[r1.y]);
    float z6 = __ldg(&g_z[r1.z]);
    float z7 = __ldg(&g_z[r1.w]);

    atomicAdd(&g_s[c0.x], z0);
    atomicAdd(&g_s[c0.y], z1);
    atomicAdd(&g_s[c0.z], z2);
    atomicAdd(&g_s[c0.w], z3);
    atomicAdd(&g_s[c1.x], z4);
    atomicAdd(&g_s[c1.y], z5);
    atomicAdd(&g_s[c1.z], z6);
    atomicAdd(&g_s[c1.w], z7);
}

// ---------------------------------------------------------------------------
// K4 (PDL): prelude: cterm reduction (hidden); post-sync minimal tail:
//           out = dinv*s + cterm.  2 coalesced loads + 1 FMA + 1 store.
// ---------------------------------------------------------------------------
__global__ void __launch_bounds__(TPB) k_final(float*       __restrict__ out,
                                               const float* __restrict__ bias,
                                               const float* __restrict__ W2,
                                               const float* __restrict__ b2)
{
    __shared__ float sred[TPB];
    int t = threadIdx.x;
    sred[t] = W2[t];                      // inputs only: safe pre-sync
    float b0 = bias[0], b20 = b2[0];
    __syncthreads();
    for (int s = TPB / 2; s > 0; s >>= 1) {
        if (t < s) sred[t] += sred[t + s];
        __syncthreads();
    }
    float cterm = b0 * sred[0] + b20;

    cudaGridDependencySynchronize();

    int i = blockIdx.x * TPB + t;
    if (i >= N_NODES) return;
    out[i] = fmaf(g_dinv[i], g_s[i], cterm);
}

// ---------------------------------------------------------------------------
extern "C" void kernel_launch(void* const* d_in, const int* in_sizes, int n_in,
                              void* d_out, int out_size)
{
    const float* x    = (const float*)d_in[0];   // [N, 48]
    const int*   ei   = (const int*)  d_in[1];   // [2, E]
    const float* W1   = (const float*)d_in[2];   // [48, 256]
    const float* bias = (const float*)d_in[3];   // [1]
    const float* W2   = (const float*)d_in[4];   // [256, 1]
    const float* b2   = (const float*)d_in[5];   // [1]
    float* out = (float*)d_out;                  // [N, 1]

    k_deg_y<<<K1_BLOCKS, TPB>>>(ei, x, W1, W2);

    cudaLaunchAttribute at;
    at.id = cudaLaunchAttributeProgrammaticStreamSerialization;
    at.val.programmaticStreamSerializationAllowed = 1;

    cudaLaunchConfig_t cfg = {};
    cfg.blockDim = dim3(TPB, 1, 1);
    cfg.attrs    = &at;
    cfg.numAttrs = 1;
    cfg.stream   = (cudaStream_t)0;

    cfg.gridDim = dim3(NODE_BLOCKS, 1, 1);
    cudaLaunchKernelEx(&cfg, k_z);

    cfg.gridDim = dim3(EDGE_BLOCKS, 1, 1);
    cudaLaunchKernelEx(&cfg, k_edges, ei);

    cfg.gridDim = dim3(NODE_BLOCKS, 1, 1);
    cudaLaunchKernelEx(&cfg, k_final, out, bias, W2, b2);
}